// round 1
// baseline (speedup 1.0000x reference)
#include <cuda_runtime.h>
#include <math.h>

#define D 128
#define NRBF 20
#define NNODES 25000
#define NEDGES 250000
#define NGRAPHS 512

// ---------------- scratch (device globals; no allocation) ----------------
__device__ float g_state0[NNODES * D];          // gathered embeddings (read-only after init)
__device__ float g_state_acc[NNODES * D];       // scattered m2 accumulator
__device__ float g_state_vec[NNODES * 3 * D];   // scattered msg_vec accumulator
__device__ float g_Up[NNODES * 3 * D];
__device__ float g_Vp[NNODES * 3 * D];
__device__ float g_UV[NNODES * D];
__device__ float g_Vn[NNODES * D];
__device__ float g_graph[NGRAPHS * D];

__device__ __forceinline__ float silu_f(float x) {
    return x / (1.0f + __expf(-x));
}

// ---------------- init: state0 = embedding[atom_types], zero accumulators ----------------
__global__ void init_kernel(const float* __restrict__ emb, const int* __restrict__ atype) {
    int stride = gridDim.x * blockDim.x;
    int total = NNODES * 3 * D;
    for (int idx = blockIdx.x * blockDim.x + threadIdx.x; idx < total; idx += stride) {
        g_state_vec[idx] = 0.0f;
        if (idx < NNODES * D) {
            int n = idx >> 7;
            int j = idx & 127;
            g_state0[idx] = emb[atype[n] * D + j];
            g_state_acc[idx] = 0.0f;
        }
        if (idx < NGRAPHS * D) g_graph[idx] = 0.0f;
    }
}

// ---------------- edge kernel: per-edge MLP + filter + scatter ----------------
// 64 edges per block, 128 threads. Thread tile 8x8. A (states/H) in smem, B (weights)
// streamed from global (L1-resident). m1 slice skipped (state_vec[from] == 0).
__global__ __launch_bounds__(128) void edge_kernel(
    const float* __restrict__ edge_vec,
    const float* __restrict__ phi_W1, const float* __restrict__ phi_b1,
    const float* __restrict__ phi_W2, const float* __restrict__ phi_b2,
    const float* __restrict__ filt_W, const float* __restrict__ filt_b,
    const int* __restrict__ node_from, const int* __restrict__ node_to)
{
    __shared__ float sA[64][132];     // gathered state rows -> later hidden H
    __shared__ float sRbf[64][NRBF];  // rbf * fc
    __shared__ float sNorm[64][3];
    __shared__ float sFc[64];
    __shared__ int   sFrom[64];
    __shared__ int   sTo[64];

    const int t = threadIdx.x;
    const int e0 = blockIdx.x * 64;
    const float PI = 3.14159265358979323846f;

    if (t < 64) {
        int e = e0 + t;
        int f = 0, to = 0;
        float nx = 0.f, ny = 0.f, nz = 0.f, fcv = 0.f;
        if (e < NEDGES) {
            f = node_from[e]; to = node_to[e];
            float x = edge_vec[3 * e + 0];
            float y = edge_vec[3 * e + 1];
            float z = edge_vec[3 * e + 2];
            float d = sqrtf(x * x + y * y + z * z);
            float inv = 1.0f / d;
            nx = x * inv; ny = y * inv; nz = z * inv;
            fcv = (d < 10.0f) ? 0.5f * (cosf(PI * d * 0.1f) + 1.0f) : 0.0f;
            float s = fcv * inv;
            #pragma unroll
            for (int r = 0; r < NRBF; r++)
                sRbf[t][r] = sinf((float)(r + 1) * PI * d * 0.1f) * s;
        } else {
            #pragma unroll
            for (int r = 0; r < NRBF; r++) sRbf[t][r] = 0.0f;
        }
        sFrom[t] = f; sTo[t] = to; sFc[t] = fcv;
        sNorm[t][0] = nx; sNorm[t][1] = ny; sNorm[t][2] = nz;
    }
    __syncthreads();

    // gather states (64 rows x 32 float4)
    for (int k = t; k < 64 * 32; k += 128) {
        int row = k >> 5, c4 = k & 31;
        const float4* src = (const float4*)(g_state0 + (size_t)sFrom[row] * D);
        *(float4*)(&sA[row][c4 * 4]) = src[c4];
    }
    __syncthreads();

    const int ty = t >> 4;        // 0..7, rows of 8
    const int tx = t & 15;        // 0..15, cols of 8
    const int r0 = ty * 8;
    const int c0 = tx * 8;

    // GEMM1: hidden = silu(S @ phi_W1 + phi_b1)
    float acc[8][8];
    #pragma unroll
    for (int i = 0; i < 8; i++)
        #pragma unroll
        for (int j = 0; j < 8; j++) acc[i][j] = 0.0f;

    for (int k = 0; k < D; k++) {
        float a[8], b[8];
        #pragma unroll
        for (int i = 0; i < 8; i++) a[i] = sA[r0 + i][k];
        float4 b0 = __ldg((const float4*)(phi_W1 + k * D + c0));
        float4 b1 = __ldg((const float4*)(phi_W1 + k * D + c0 + 4));
        b[0] = b0.x; b[1] = b0.y; b[2] = b0.z; b[3] = b0.w;
        b[4] = b1.x; b[5] = b1.y; b[6] = b1.z; b[7] = b1.w;
        #pragma unroll
        for (int i = 0; i < 8; i++)
            #pragma unroll
            for (int j = 0; j < 8; j++) acc[i][j] += a[i] * b[j];
    }
    __syncthreads();   // all reads of sA done before overwrite
    #pragma unroll
    for (int j = 0; j < 8; j++) {
        float bias = __ldg(&phi_b1[c0 + j]);
        #pragma unroll
        for (int i = 0; i < 8; i++) {
            float x = acc[i][j] + bias;
            sA[r0 + i][c0 + j] = silu_f(x);
        }
    }
    __syncthreads();

    // Phase 2: half 0 -> m2 (phi cols 128..255), half 1 -> m3 (256..383)
    #pragma unroll 1
    for (int half = 0; half < 2; half++) {
        const int cb = D + half * D;

        // W_out[j] = (rbf@filt_W + filt_b)*fc  == rbf_fc @ filt_W + fc*filt_b
        float wout[8][8];
        #pragma unroll
        for (int j = 0; j < 8; j++) {
            float fb = __ldg(&filt_b[cb + c0 + j]);
            #pragma unroll
            for (int i = 0; i < 8; i++) wout[i][j] = sFc[r0 + i] * fb;
        }
        for (int r = 0; r < NRBF; r++) {
            float a[8];
            #pragma unroll
            for (int i = 0; i < 8; i++) a[i] = sRbf[r0 + i][r];
            float4 f0 = __ldg((const float4*)(filt_W + r * 384 + cb + c0));
            float4 f1 = __ldg((const float4*)(filt_W + r * 384 + cb + c0 + 4));
            float b[8] = {f0.x, f0.y, f0.z, f0.w, f1.x, f1.y, f1.z, f1.w};
            #pragma unroll
            for (int i = 0; i < 8; i++)
                #pragma unroll
                for (int j = 0; j < 8; j++) wout[i][j] += a[i] * b[j];
        }

        // GEMM2: H @ phi_W2[:, cb:cb+128]
        float acc2[8][8];
        #pragma unroll
        for (int i = 0; i < 8; i++)
            #pragma unroll
            for (int j = 0; j < 8; j++) acc2[i][j] = 0.0f;
        for (int k = 0; k < D; k++) {
            float a[8];
            #pragma unroll
            for (int i = 0; i < 8; i++) a[i] = sA[r0 + i][k];
            float4 b0 = __ldg((const float4*)(phi_W2 + k * 384 + cb + c0));
            float4 b1 = __ldg((const float4*)(phi_W2 + k * 384 + cb + c0 + 4));
            float b[8] = {b0.x, b0.y, b0.z, b0.w, b1.x, b1.y, b1.z, b1.w};
            #pragma unroll
            for (int i = 0; i < 8; i++)
                #pragma unroll
                for (int j = 0; j < 8; j++) acc2[i][j] += a[i] * b[j];
        }

        if (half == 0) {
            #pragma unroll
            for (int i = 0; i < 8; i++) {
                int e = e0 + r0 + i;
                if (e < NEDGES) {
                    float* dst = g_state_acc + (size_t)sTo[r0 + i] * D + c0;
                    #pragma unroll
                    for (int j = 0; j < 8; j++) {
                        float pf = (acc2[i][j] + __ldg(&phi_b2[cb + c0 + j])) * wout[i][j];
                        atomicAdd(dst + j, pf);
                    }
                }
            }
        } else {
            #pragma unroll
            for (int i = 0; i < 8; i++) {
                int e = e0 + r0 + i;
                if (e < NEDGES) {
                    float n0 = sNorm[r0 + i][0];
                    float n1 = sNorm[r0 + i][1];
                    float n2 = sNorm[r0 + i][2];
                    float* dst = g_state_vec + (size_t)sTo[r0 + i] * (3 * D) + c0;
                    #pragma unroll
                    for (int j = 0; j < 8; j++) {
                        float pf = (acc2[i][j] + __ldg(&phi_b2[cb + c0 + j])) * wout[i][j];
                        atomicAdd(dst + j,           n0 * pf);
                        atomicAdd(dst + D + j,       n1 * pf);
                        atomicAdd(dst + 2 * D + j,   n2 * pf);
                    }
                }
            }
        }
    }
}

// ---------------- Up/Vp: rows = (node,c) flattened, 75000 x 128 @ 128x128 (x2) ----------------
__global__ __launch_bounds__(256) void uv_gemm_kernel(
    const float* __restrict__ U_W, const float* __restrict__ V_W)
{
    __shared__ float sA[64][132];
    const int t = threadIdx.x;
    const int rbase = blockIdx.x * 64;
    const int NR = NNODES * 3;

    for (int k = t; k < 64 * 32; k += 256) {
        int row = k >> 5, c4 = k & 31;
        int r = rbase + row;
        float4 v = make_float4(0.f, 0.f, 0.f, 0.f);
        if (r < NR) v = ((const float4*)(g_state_vec + (size_t)r * D))[c4];
        *(float4*)(&sA[row][c4 * 4]) = v;
    }
    __syncthreads();

    const int ty = t >> 4;        // 0..15, rows of 4
    const int tx = t & 15;        // cols of 8
    const int r0 = ty * 4, c0 = tx * 8;

    float au[4][8], av[4][8];
    #pragma unroll
    for (int i = 0; i < 4; i++)
        #pragma unroll
        for (int j = 0; j < 8; j++) { au[i][j] = 0.f; av[i][j] = 0.f; }

    for (int k = 0; k < D; k++) {
        float a[4];
        #pragma unroll
        for (int i = 0; i < 4; i++) a[i] = sA[r0 + i][k];
        float4 u0 = __ldg((const float4*)(U_W + k * D + c0));
        float4 u1 = __ldg((const float4*)(U_W + k * D + c0 + 4));
        float4 v0 = __ldg((const float4*)(V_W + k * D + c0));
        float4 v1 = __ldg((const float4*)(V_W + k * D + c0 + 4));
        float bu[8] = {u0.x, u0.y, u0.z, u0.w, u1.x, u1.y, u1.z, u1.w};
        float bv[8] = {v0.x, v0.y, v0.z, v0.w, v1.x, v1.y, v1.z, v1.w};
        #pragma unroll
        for (int i = 0; i < 4; i++)
            #pragma unroll
            for (int j = 0; j < 8; j++) {
                au[i][j] += a[i] * bu[j];
                av[i][j] += a[i] * bv[j];
            }
    }

    #pragma unroll
    for (int i = 0; i < 4; i++) {
        int r = rbase + r0 + i;
        if (r < NR) {
            float4* du = (float4*)(g_Up + (size_t)r * D + c0);
            float4* dv = (float4*)(g_Vp + (size_t)r * D + c0);
            du[0] = make_float4(au[i][0], au[i][1], au[i][2], au[i][3]);
            du[1] = make_float4(au[i][4], au[i][5], au[i][6], au[i][7]);
            dv[0] = make_float4(av[i][0], av[i][1], av[i][2], av[i][3]);
            dv[1] = make_float4(av[i][4], av[i][5], av[i][6], av[i][7]);
        }
    }
}

// ---------------- UV = sum_c Up*Vp ; Vn = ||Vp|| over c ----------------
__global__ void uv_reduce_kernel() {
    int idx = blockIdx.x * blockDim.x + threadIdx.x;
    if (idx >= NNODES * D) return;
    int n = idx >> 7, j = idx & 127;
    size_t b = (size_t)n * (3 * D) + j;
    float u0 = g_Up[b], u1 = g_Up[b + D], u2 = g_Up[b + 2 * D];
    float v0 = g_Vp[b], v1 = g_Vp[b + D], v2 = g_Vp[b + 2 * D];
    g_UV[idx] = u0 * v0 + u1 * v1 + u2 * v2;
    g_Vn[idx] = sqrtf(v0 * v0 + v1 * v1 + v2 * v2);
}

// ---------------- node update MLP + segment-sum into graph accumulator ----------------
// 32 nodes / block, 128 threads, thread tile 4x8. h=[Vn, state] (K=256). a_vv skipped.
__global__ __launch_bounds__(128) void update_kernel(
    const float* __restrict__ upd_W1, const float* __restrict__ upd_b1,
    const float* __restrict__ upd_W2, const float* __restrict__ upd_b2,
    const int* __restrict__ node_graph_index)
{
    __shared__ float sA[32][260];   // cols 0..127: Vn (later hid), 128..255: state
    const int t = threadIdx.x;
    const int n0 = blockIdx.x * 32;

    for (int k = t; k < 32 * 64; k += 128) {
        int row = k >> 6, c4 = k & 63;
        int n = n0 + row;
        float4 v = make_float4(0.f, 0.f, 0.f, 0.f);
        if (n < NNODES) {
            if (c4 < 32) {
                v = ((const float4*)(g_Vn + (size_t)n * D))[c4];
            } else {
                float4 s0 = ((const float4*)(g_state0 + (size_t)n * D))[c4 - 32];
                float4 s1 = ((const float4*)(g_state_acc + (size_t)n * D))[c4 - 32];
                v = make_float4(s0.x + s1.x, s0.y + s1.y, s0.z + s1.z, s0.w + s1.w);
            }
        }
        *(float4*)(&sA[row][c4 * 4]) = v;
    }
    __syncthreads();

    const int ty = t >> 4;        // 0..7, rows of 4
    const int tx = t & 15;        // cols of 8
    const int r0 = ty * 4, c0 = tx * 8;

    // GEMM1: hid = silu(h @ upd_W1 + b1), K = 256
    float acc[4][8];
    #pragma unroll
    for (int i = 0; i < 4; i++)
        #pragma unroll
        for (int j = 0; j < 8; j++) acc[i][j] = 0.f;
    for (int k = 0; k < 2 * D; k++) {
        float a[4];
        #pragma unroll
        for (int i = 0; i < 4; i++) a[i] = sA[r0 + i][k];
        float4 b0 = __ldg((const float4*)(upd_W1 + k * D + c0));
        float4 b1 = __ldg((const float4*)(upd_W1 + k * D + c0 + 4));
        float b[8] = {b0.x, b0.y, b0.z, b0.w, b1.x, b1.y, b1.z, b1.w};
        #pragma unroll
        for (int i = 0; i < 4; i++)
            #pragma unroll
            for (int j = 0; j < 8; j++) acc[i][j] += a[i] * b[j];
    }
    __syncthreads();
    #pragma unroll
    for (int j = 0; j < 8; j++) {
        float bias = __ldg(&upd_b1[c0 + j]);
        #pragma unroll
        for (int i = 0; i < 4; i++) sA[r0 + i][c0 + j] = silu_f(acc[i][j] + bias);
    }
    __syncthreads();

    float res[4][8];

    // a_sv: hid @ upd_W2[:, 128:256];  res = state + UV * a_sv
    #pragma unroll
    for (int i = 0; i < 4; i++)
        #pragma unroll
        for (int j = 0; j < 8; j++) acc[i][j] = 0.f;
    for (int k = 0; k < D; k++) {
        float a[4];
        #pragma unroll
        for (int i = 0; i < 4; i++) a[i] = sA[r0 + i][k];
        float4 b0 = __ldg((const float4*)(upd_W2 + k * 384 + D + c0));
        float4 b1 = __ldg((const float4*)(upd_W2 + k * 384 + D + c0 + 4));
        float b[8] = {b0.x, b0.y, b0.z, b0.w, b1.x, b1.y, b1.z, b1.w};
        #pragma unroll
        for (int i = 0; i < 4; i++)
            #pragma unroll
            for (int j = 0; j < 8; j++) acc[i][j] += a[i] * b[j];
    }
    #pragma unroll
    for (int i = 0; i < 4; i++) {
        int n = n0 + r0 + i;
        #pragma unroll
        for (int j = 0; j < 8; j++) {
            float uv = (n < NNODES) ? g_UV[(size_t)n * D + c0 + j] : 0.f;
            float a_sv = acc[i][j] + __ldg(&upd_b2[D + c0 + j]);
            res[i][j] = sA[r0 + i][D + c0 + j] + uv * a_sv;
        }
    }

    // a_ss: hid @ upd_W2[:, 256:384];  res += a_ss
    #pragma unroll
    for (int i = 0; i < 4; i++)
        #pragma unroll
        for (int j = 0; j < 8; j++) acc[i][j] = 0.f;
    for (int k = 0; k < D; k++) {
        float a[4];
        #pragma unroll
        for (int i = 0; i < 4; i++) a[i] = sA[r0 + i][k];
        float4 b0 = __ldg((const float4*)(upd_W2 + k * 384 + 2 * D + c0));
        float4 b1 = __ldg((const float4*)(upd_W2 + k * 384 + 2 * D + c0 + 4));
        float b[8] = {b0.x, b0.y, b0.z, b0.w, b1.x, b1.y, b1.z, b1.w};
        #pragma unroll
        for (int i = 0; i < 4; i++)
            #pragma unroll
            for (int j = 0; j < 8; j++) acc[i][j] += a[i] * b[j];
    }

    int base = __ldg(&node_graph_index[0]);
    #pragma unroll
    for (int i = 0; i < 4; i++) {
        int n = n0 + r0 + i;
        if (n < NNODES) {
            int g = __ldg(&node_graph_index[n]) - base;
            float* dst = g_graph + (size_t)g * D + c0;
            #pragma unroll
            for (int j = 0; j < 8; j++) {
                float v = res[i][j] + acc[i][j] + __ldg(&upd_b2[2 * D + c0 + j]);
                atomicAdd(dst + j, v);
            }
        }
    }
}

// ---------------- output MLP: 512 graphs ----------------
__global__ void out_kernel(
    const float* __restrict__ out_W1, const float* __restrict__ out_b1,
    const float* __restrict__ out_W2, const float* __restrict__ out_b2,
    float* __restrict__ out)
{
    __shared__ float sG[D];
    __shared__ float sRed[D];
    const int g = blockIdx.x;
    const int t = threadIdx.x;
    sG[t] = g_graph[(size_t)g * D + t];
    __syncthreads();
    float x = 0.f;
    #pragma unroll 8
    for (int k = 0; k < D; k++) x += sG[k] * __ldg(&out_W1[k * D + t]);
    x += __ldg(&out_b1[t]);
    float p = silu_f(x) * __ldg(&out_W2[t]);
    sRed[t] = p;
    __syncthreads();
    for (int s = 64; s > 0; s >>= 1) {
        if (t < s) sRed[t] += sRed[t + s];
        __syncthreads();
    }
    if (t == 0) out[g] = sRed[0] + __ldg(&out_b2[0]);
}

// ---------------- launch ----------------
extern "C" void kernel_launch(void* const* d_in, const int* in_sizes, int n_in,
                              void* d_out, int out_size)
{
    const float* edge_vec  = (const float*)d_in[0];
    const float* embedding = (const float*)d_in[1];
    const float* phi_W1 = (const float*)d_in[2];
    const float* phi_b1 = (const float*)d_in[3];
    const float* phi_W2 = (const float*)d_in[4];
    const float* phi_b2 = (const float*)d_in[5];
    const float* filt_W = (const float*)d_in[6];
    const float* filt_b = (const float*)d_in[7];
    const float* upd_W1 = (const float*)d_in[8];
    const float* upd_b1 = (const float*)d_in[9];
    const float* upd_W2 = (const float*)d_in[10];
    const float* upd_b2 = (const float*)d_in[11];
    const float* out_W1 = (const float*)d_in[12];
    const float* out_b1 = (const float*)d_in[13];
    const float* out_W2 = (const float*)d_in[14];
    const float* out_b2 = (const float*)d_in[15];
    const float* U_W    = (const float*)d_in[16];
    const float* V_W    = (const float*)d_in[17];
    const int* atom_types = (const int*)d_in[18];
    const int* node_from  = (const int*)d_in[19];
    const int* node_to    = (const int*)d_in[20];
    const int* node_graph_index = (const int*)d_in[21];
    float* out = (float*)d_out;

    init_kernel<<<2048, 256>>>(embedding, atom_types);
    edge_kernel<<<(NEDGES + 63) / 64, 128>>>(edge_vec, phi_W1, phi_b1, phi_W2, phi_b2,
                                             filt_W, filt_b, node_from, node_to);
    uv_gemm_kernel<<<(NNODES * 3 + 63) / 64, 256>>>(U_W, V_W);
    uv_reduce_kernel<<<(NNODES * D + 255) / 256, 256>>>();
    update_kernel<<<(NNODES + 31) / 32, 128>>>(upd_W1, upd_b1, upd_W2, upd_b2, node_graph_index);
    out_kernel<<<NGRAPHS, D>>>(out_W1, out_b1, out_W2, out_b2, out);
}

// round 2
// speedup vs baseline: 2.1162x; 2.1162x over previous
#include <cuda_runtime.h>
#include <math.h>

#define D 128
#define NRBF 20
#define NNODES 25000
#define NEDGES 250000
#define NGRAPHS 512

// ---------------- scratch (device globals; no allocation) ----------------
__device__ float g_state0[NNODES * D];          // gathered embeddings (read-only after init)
__device__ float g_state_acc[NNODES * D];       // scattered m2 accumulator
__device__ float g_state_vec[NNODES * 3 * D];   // scattered msg_vec accumulator
__device__ float g_phi[NNODES * 2 * D];         // per-node phi output, cols 128..383 (m2|m3)
__device__ float g_Up[NNODES * 3 * D];
__device__ float g_Vp[NNODES * 3 * D];
__device__ float g_UV[NNODES * D];
__device__ float g_Vn[NNODES * D];
__device__ float g_graph[NGRAPHS * D];

__device__ __forceinline__ float silu_f(float x) {
    return x / (1.0f + __expf(-x));
}

// ---------------- init: state0 = embedding[atom_types], zero accumulators ----------------
__global__ void init_kernel(const float* __restrict__ emb, const int* __restrict__ atype) {
    int stride = gridDim.x * blockDim.x;
    int total = NNODES * 3 * D;
    for (int idx = blockIdx.x * blockDim.x + threadIdx.x; idx < total; idx += stride) {
        g_state_vec[idx] = 0.0f;
        if (idx < NNODES * D) {
            int n = idx >> 7;
            int j = idx & 127;
            g_state0[idx] = emb[atype[n] * D + j];
            g_state_acc[idx] = 0.0f;
        }
        if (idx < NGRAPHS * D) g_graph[idx] = 0.0f;
    }
}

// ---------------- per-NODE phi MLP (hoisted out of the edge loop) ----------------
// phi[n, 0:256] = (silu(state0[n]@phi_W1 + b1) @ phi_W2 + b2)[128:384]
// 64 nodes / block, 128 threads, 8x8 thread tiles.
__global__ __launch_bounds__(128) void node_phi_kernel(
    const float* __restrict__ phi_W1, const float* __restrict__ phi_b1,
    const float* __restrict__ phi_W2, const float* __restrict__ phi_b2)
{
    __shared__ float sA[64][132];
    const int t = threadIdx.x;
    const int n0 = blockIdx.x * 64;

    // load 64 node states
    for (int k = t; k < 64 * 32; k += 128) {
        int row = k >> 5, c4 = k & 31;
        int n = n0 + row;
        float4 v = make_float4(0.f, 0.f, 0.f, 0.f);
        if (n < NNODES) v = ((const float4*)(g_state0 + (size_t)n * D))[c4];
        *(float4*)(&sA[row][c4 * 4]) = v;
    }
    __syncthreads();

    const int ty = t >> 4;     // 0..7 (8 rows)
    const int tx = t & 15;     // 0..15 (8 cols)
    const int r0 = ty * 8, c0 = tx * 8;

    // GEMM1: hidden = silu(S @ phi_W1 + b1)
    float acc[8][8];
    #pragma unroll
    for (int i = 0; i < 8; i++)
        #pragma unroll
        for (int j = 0; j < 8; j++) acc[i][j] = 0.0f;
    for (int k = 0; k < D; k++) {
        float a[8];
        #pragma unroll
        for (int i = 0; i < 8; i++) a[i] = sA[r0 + i][k];
        float4 b0 = __ldg((const float4*)(phi_W1 + k * D + c0));
        float4 b1 = __ldg((const float4*)(phi_W1 + k * D + c0 + 4));
        float b[8] = {b0.x, b0.y, b0.z, b0.w, b1.x, b1.y, b1.z, b1.w};
        #pragma unroll
        for (int i = 0; i < 8; i++)
            #pragma unroll
            for (int j = 0; j < 8; j++) acc[i][j] += a[i] * b[j];
    }
    __syncthreads();
    #pragma unroll
    for (int j = 0; j < 8; j++) {
        float bias = __ldg(&phi_b1[c0 + j]);
        #pragma unroll
        for (int i = 0; i < 8; i++) sA[r0 + i][c0 + j] = silu_f(acc[i][j] + bias);
    }
    __syncthreads();

    // GEMM2: H @ phi_W2[:, 128:384]  (two 128-col passes: m2 then m3)
    #pragma unroll 1
    for (int half = 0; half < 2; half++) {
        const int cb = D + half * D;
        float acc2[8][8];
        #pragma unroll
        for (int i = 0; i < 8; i++)
            #pragma unroll
            for (int j = 0; j < 8; j++) acc2[i][j] = 0.0f;
        for (int k = 0; k < D; k++) {
            float a[8];
            #pragma unroll
            for (int i = 0; i < 8; i++) a[i] = sA[r0 + i][k];
            float4 b0 = __ldg((const float4*)(phi_W2 + k * 384 + cb + c0));
            float4 b1 = __ldg((const float4*)(phi_W2 + k * 384 + cb + c0 + 4));
            float b[8] = {b0.x, b0.y, b0.z, b0.w, b1.x, b1.y, b1.z, b1.w};
            #pragma unroll
            for (int i = 0; i < 8; i++)
                #pragma unroll
                for (int j = 0; j < 8; j++) acc2[i][j] += a[i] * b[j];
        }
        #pragma unroll
        for (int i = 0; i < 8; i++) {
            int n = n0 + r0 + i;
            if (n < NNODES) {
                float4* dst = (float4*)(g_phi + (size_t)n * 256 + half * D + c0);
                float b4 = __ldg(&phi_b2[cb + c0 + 0]);
                float b5 = __ldg(&phi_b2[cb + c0 + 1]);
                float b6 = __ldg(&phi_b2[cb + c0 + 2]);
                float b7 = __ldg(&phi_b2[cb + c0 + 3]);
                dst[0] = make_float4(acc2[i][0] + b4, acc2[i][1] + b5, acc2[i][2] + b6, acc2[i][3] + b7);
                b4 = __ldg(&phi_b2[cb + c0 + 4]);
                b5 = __ldg(&phi_b2[cb + c0 + 5]);
                b6 = __ldg(&phi_b2[cb + c0 + 6]);
                b7 = __ldg(&phi_b2[cb + c0 + 7]);
                dst[1] = make_float4(acc2[i][4] + b4, acc2[i][5] + b5, acc2[i][6] + b6, acc2[i][7] + b7);
            }
        }
    }
}

// ---------------- edge kernel: RBF filter + gather phi[from] + scatter ----------------
// 8 edges / block (250000 % 8 == 0), 256 threads = 8 x 32; each thread owns 8 of
// the 256 filter columns. Scatter via float4 atomicAdd (RED.128).
__global__ __launch_bounds__(256) void edge_kernel(
    const float* __restrict__ edge_vec,
    const float* __restrict__ filt_W, const float* __restrict__ filt_b,
    const int* __restrict__ node_from, const int* __restrict__ node_to)
{
    __shared__ float sRbf[8][20];   // rbf * fc / d
    __shared__ float sFc[8];
    __shared__ float sDist[8];
    __shared__ float sNorm[8][3];
    __shared__ int   sFrom[8];
    __shared__ int   sTo[8];

    const int t = threadIdx.x;
    const int e0 = blockIdx.x * 8;
    const float PI = 3.14159265358979323846f;

    if (t < 8) {
        int e = e0 + t;
        float x = edge_vec[3 * e + 0];
        float y = edge_vec[3 * e + 1];
        float z = edge_vec[3 * e + 2];
        float d = sqrtf(x * x + y * y + z * z);
        float inv = 1.0f / d;
        float fcv = (d < 10.0f) ? 0.5f * (cosf(PI * d * 0.1f) + 1.0f) : 0.0f;
        sDist[t] = d;
        sFc[t] = fcv * inv;            // combined scale for rbf
        sNorm[t][0] = x * inv; sNorm[t][1] = y * inv; sNorm[t][2] = z * inv;
        sFrom[t] = node_from[e];
        sTo[t] = node_to[e];
    }
    __syncthreads();
    if (t < 160) {
        int le = t / 20, r = t % 20;
        sRbf[le][r] = sinf((float)(r + 1) * PI * sDist[le] * 0.1f) * sFc[le];
    }
    __syncthreads();

    const int le = t >> 5;          // edge within block
    const int j0 = (t & 31) << 3;   // column group 0..248

    // fc for bias term: sFc holds fc/d; recover fc = sFc * d
    const float fc = sFc[le] * sDist[le];

    float w[8];
    #pragma unroll
    for (int j = 0; j < 8; j++) w[j] = fc * __ldg(&filt_b[128 + j0 + j]);
    #pragma unroll
    for (int r = 0; r < NRBF; r++) {
        float a = sRbf[le][r];
        float4 b0 = __ldg((const float4*)(filt_W + r * 384 + 128 + j0));
        float4 b1 = __ldg((const float4*)(filt_W + r * 384 + 128 + j0 + 4));
        w[0] += a * b0.x; w[1] += a * b0.y; w[2] += a * b0.z; w[3] += a * b0.w;
        w[4] += a * b1.x; w[5] += a * b1.y; w[6] += a * b1.z; w[7] += a * b1.w;
    }

    const float4* ph = (const float4*)(g_phi + (size_t)sFrom[le] * 256 + j0);
    float4 p0 = ph[0];
    float4 p1 = ph[1];
    float pf[8];
    pf[0] = p0.x * w[0]; pf[1] = p0.y * w[1]; pf[2] = p0.z * w[2]; pf[3] = p0.w * w[3];
    pf[4] = p1.x * w[4]; pf[5] = p1.y * w[5]; pf[6] = p1.z * w[6]; pf[7] = p1.w * w[7];

    const int to = sTo[le];
    if (j0 < 128) {
        // m2 -> state accumulator
        float4* dst = (float4*)(g_state_acc + (size_t)to * D + j0);
        atomicAdd(dst,     make_float4(pf[0], pf[1], pf[2], pf[3]));
        atomicAdd(dst + 1, make_float4(pf[4], pf[5], pf[6], pf[7]));
    } else {
        // m3 -> msg_vec = normalized[d] * m3[j]
        const int jj = j0 - 128;
        float n0 = sNorm[le][0], n1 = sNorm[le][1], n2 = sNorm[le][2];
        float* base = g_state_vec + (size_t)to * (3 * D) + jj;
        atomicAdd((float4*)(base),               make_float4(n0 * pf[0], n0 * pf[1], n0 * pf[2], n0 * pf[3]));
        atomicAdd((float4*)(base + 4),           make_float4(n0 * pf[4], n0 * pf[5], n0 * pf[6], n0 * pf[7]));
        atomicAdd((float4*)(base + D),           make_float4(n1 * pf[0], n1 * pf[1], n1 * pf[2], n1 * pf[3]));
        atomicAdd((float4*)(base + D + 4),       make_float4(n1 * pf[4], n1 * pf[5], n1 * pf[6], n1 * pf[7]));
        atomicAdd((float4*)(base + 2 * D),       make_float4(n2 * pf[0], n2 * pf[1], n2 * pf[2], n2 * pf[3]));
        atomicAdd((float4*)(base + 2 * D + 4),   make_float4(n2 * pf[4], n2 * pf[5], n2 * pf[6], n2 * pf[7]));
    }
}

// ---------------- Up/Vp: rows = (node,c) flattened, 75000 x 128 @ 128x128 (x2) ----------------
__global__ __launch_bounds__(256) void uv_gemm_kernel(
    const float* __restrict__ U_W, const float* __restrict__ V_W)
{
    __shared__ float sA[64][132];
    const int t = threadIdx.x;
    const int rbase = blockIdx.x * 64;
    const int NR = NNODES * 3;

    for (int k = t; k < 64 * 32; k += 256) {
        int row = k >> 5, c4 = k & 31;
        int r = rbase + row;
        float4 v = make_float4(0.f, 0.f, 0.f, 0.f);
        if (r < NR) v = ((const float4*)(g_state_vec + (size_t)r * D))[c4];
        *(float4*)(&sA[row][c4 * 4]) = v;
    }
    __syncthreads();

    const int ty = t >> 4;        // 0..15, rows of 4
    const int tx = t & 15;        // cols of 8
    const int r0 = ty * 4, c0 = tx * 8;

    float au[4][8], av[4][8];
    #pragma unroll
    for (int i = 0; i < 4; i++)
        #pragma unroll
        for (int j = 0; j < 8; j++) { au[i][j] = 0.f; av[i][j] = 0.f; }

    for (int k = 0; k < D; k++) {
        float a[4];
        #pragma unroll
        for (int i = 0; i < 4; i++) a[i] = sA[r0 + i][k];
        float4 u0 = __ldg((const float4*)(U_W + k * D + c0));
        float4 u1 = __ldg((const float4*)(U_W + k * D + c0 + 4));
        float4 v0 = __ldg((const float4*)(V_W + k * D + c0));
        float4 v1 = __ldg((const float4*)(V_W + k * D + c0 + 4));
        float bu[8] = {u0.x, u0.y, u0.z, u0.w, u1.x, u1.y, u1.z, u1.w};
        float bv[8] = {v0.x, v0.y, v0.z, v0.w, v1.x, v1.y, v1.z, v1.w};
        #pragma unroll
        for (int i = 0; i < 4; i++)
            #pragma unroll
            for (int j = 0; j < 8; j++) {
                au[i][j] += a[i] * bu[j];
                av[i][j] += a[i] * bv[j];
            }
    }

    #pragma unroll
    for (int i = 0; i < 4; i++) {
        int r = rbase + r0 + i;
        if (r < NR) {
            float4* du = (float4*)(g_Up + (size_t)r * D + c0);
            float4* dv = (float4*)(g_Vp + (size_t)r * D + c0);
            du[0] = make_float4(au[i][0], au[i][1], au[i][2], au[i][3]);
            du[1] = make_float4(au[i][4], au[i][5], au[i][6], au[i][7]);
            dv[0] = make_float4(av[i][0], av[i][1], av[i][2], av[i][3]);
            dv[1] = make_float4(av[i][4], av[i][5], av[i][6], av[i][7]);
        }
    }
}

// ---------------- UV = sum_c Up*Vp ; Vn = ||Vp|| over c ----------------
__global__ void uv_reduce_kernel() {
    int idx = blockIdx.x * blockDim.x + threadIdx.x;
    if (idx >= NNODES * D) return;
    int n = idx >> 7, j = idx & 127;
    size_t b = (size_t)n * (3 * D) + j;
    float u0 = g_Up[b], u1 = g_Up[b + D], u2 = g_Up[b + 2 * D];
    float v0 = g_Vp[b], v1 = g_Vp[b + D], v2 = g_Vp[b + 2 * D];
    g_UV[idx] = u0 * v0 + u1 * v1 + u2 * v2;
    g_Vn[idx] = sqrtf(v0 * v0 + v1 * v1 + v2 * v2);
}

// ---------------- node update MLP + segment-sum into graph accumulator ----------------
__global__ __launch_bounds__(128) void update_kernel(
    const float* __restrict__ upd_W1, const float* __restrict__ upd_b1,
    const float* __restrict__ upd_W2, const float* __restrict__ upd_b2,
    const int* __restrict__ node_graph_index)
{
    __shared__ float sA[32][260];   // cols 0..127: Vn (later hid), 128..255: state
    const int t = threadIdx.x;
    const int n0 = blockIdx.x * 32;

    for (int k = t; k < 32 * 64; k += 128) {
        int row = k >> 6, c4 = k & 63;
        int n = n0 + row;
        float4 v = make_float4(0.f, 0.f, 0.f, 0.f);
        if (n < NNODES) {
            if (c4 < 32) {
                v = ((const float4*)(g_Vn + (size_t)n * D))[c4];
            } else {
                float4 s0 = ((const float4*)(g_state0 + (size_t)n * D))[c4 - 32];
                float4 s1 = ((const float4*)(g_state_acc + (size_t)n * D))[c4 - 32];
                v = make_float4(s0.x + s1.x, s0.y + s1.y, s0.z + s1.z, s0.w + s1.w);
            }
        }
        *(float4*)(&sA[row][c4 * 4]) = v;
    }
    __syncthreads();

    const int ty = t >> 4;
    const int tx = t & 15;
    const int r0 = ty * 4, c0 = tx * 8;

    // GEMM1: hid = silu(h @ upd_W1 + b1), K = 256
    float acc[4][8];
    #pragma unroll
    for (int i = 0; i < 4; i++)
        #pragma unroll
        for (int j = 0; j < 8; j++) acc[i][j] = 0.f;
    for (int k = 0; k < 2 * D; k++) {
        float a[4];
        #pragma unroll
        for (int i = 0; i < 4; i++) a[i] = sA[r0 + i][k];
        float4 b0 = __ldg((const float4*)(upd_W1 + k * D + c0));
        float4 b1 = __ldg((const float4*)(upd_W1 + k * D + c0 + 4));
        float b[8] = {b0.x, b0.y, b0.z, b0.w, b1.x, b1.y, b1.z, b1.w};
        #pragma unroll
        for (int i = 0; i < 4; i++)
            #pragma unroll
            for (int j = 0; j < 8; j++) acc[i][j] += a[i] * b[j];
    }
    __syncthreads();
    #pragma unroll
    for (int j = 0; j < 8; j++) {
        float bias = __ldg(&upd_b1[c0 + j]);
        #pragma unroll
        for (int i = 0; i < 4; i++) sA[r0 + i][c0 + j] = silu_f(acc[i][j] + bias);
    }
    __syncthreads();

    float res[4][8];

    // a_sv: hid @ upd_W2[:, 128:256];  res = state + UV * a_sv
    #pragma unroll
    for (int i = 0; i < 4; i++)
        #pragma unroll
        for (int j = 0; j < 8; j++) acc[i][j] = 0.f;
    for (int k = 0; k < D; k++) {
        float a[4];
        #pragma unroll
        for (int i = 0; i < 4; i++) a[i] = sA[r0 + i][k];
        float4 b0 = __ldg((const float4*)(upd_W2 + k * 384 + D + c0));
        float4 b1 = __ldg((const float4*)(upd_W2 + k * 384 + D + c0 + 4));
        float b[8] = {b0.x, b0.y, b0.z, b0.w, b1.x, b1.y, b1.z, b1.w};
        #pragma unroll
        for (int i = 0; i < 4; i++)
            #pragma unroll
            for (int j = 0; j < 8; j++) acc[i][j] += a[i] * b[j];
    }
    #pragma unroll
    for (int i = 0; i < 4; i++) {
        int n = n0 + r0 + i;
        #pragma unroll
        for (int j = 0; j < 8; j++) {
            float uv = (n < NNODES) ? g_UV[(size_t)n * D + c0 + j] : 0.f;
            float a_sv = acc[i][j] + __ldg(&upd_b2[D + c0 + j]);
            res[i][j] = sA[r0 + i][D + c0 + j] + uv * a_sv;
        }
    }

    // a_ss: hid @ upd_W2[:, 256:384];  res += a_ss
    #pragma unroll
    for (int i = 0; i < 4; i++)
        #pragma unroll
        for (int j = 0; j < 8; j++) acc[i][j] = 0.f;
    for (int k = 0; k < D; k++) {
        float a[4];
        #pragma unroll
        for (int i = 0; i < 4; i++) a[i] = sA[r0 + i][k];
        float4 b0 = __ldg((const float4*)(upd_W2 + k * 384 + 2 * D + c0));
        float4 b1 = __ldg((const float4*)(upd_W2 + k * 384 + 2 * D + c0 + 4));
        float b[8] = {b0.x, b0.y, b0.z, b0.w, b1.x, b1.y, b1.z, b1.w};
        #pragma unroll
        for (int i = 0; i < 4; i++)
            #pragma unroll
            for (int j = 0; j < 8; j++) acc[i][j] += a[i] * b[j];
    }

    int base = __ldg(&node_graph_index[0]);
    #pragma unroll
    for (int i = 0; i < 4; i++) {
        int n = n0 + r0 + i;
        if (n < NNODES) {
            int g = __ldg(&node_graph_index[n]) - base;
            float* dst = g_graph + (size_t)g * D + c0;
            float v0 = res[i][0] + acc[i][0] + __ldg(&upd_b2[2 * D + c0 + 0]);
            float v1 = res[i][1] + acc[i][1] + __ldg(&upd_b2[2 * D + c0 + 1]);
            float v2 = res[i][2] + acc[i][2] + __ldg(&upd_b2[2 * D + c0 + 2]);
            float v3 = res[i][3] + acc[i][3] + __ldg(&upd_b2[2 * D + c0 + 3]);
            atomicAdd((float4*)dst, make_float4(v0, v1, v2, v3));
            v0 = res[i][4] + acc[i][4] + __ldg(&upd_b2[2 * D + c0 + 4]);
            v1 = res[i][5] + acc[i][5] + __ldg(&upd_b2[2 * D + c0 + 5]);
            v2 = res[i][6] + acc[i][6] + __ldg(&upd_b2[2 * D + c0 + 6]);
            v3 = res[i][7] + acc[i][7] + __ldg(&upd_b2[2 * D + c0 + 7]);
            atomicAdd((float4*)(dst + 4), make_float4(v0, v1, v2, v3));
        }
    }
}

// ---------------- output MLP: 512 graphs ----------------
__global__ void out_kernel(
    const float* __restrict__ out_W1, const float* __restrict__ out_b1,
    const float* __restrict__ out_W2, const float* __restrict__ out_b2,
    float* __restrict__ out)
{
    __shared__ float sG[D];
    __shared__ float sRed[D];
    const int g = blockIdx.x;
    const int t = threadIdx.x;
    sG[t] = g_graph[(size_t)g * D + t];
    __syncthreads();
    float x = 0.f;
    #pragma unroll 8
    for (int k = 0; k < D; k++) x += sG[k] * __ldg(&out_W1[k * D + t]);
    x += __ldg(&out_b1[t]);
    float p = silu_f(x) * __ldg(&out_W2[t]);
    sRed[t] = p;
    __syncthreads();
    for (int s = 64; s > 0; s >>= 1) {
        if (t < s) sRed[t] += sRed[t + s];
        __syncthreads();
    }
    if (t == 0) out[g] = sRed[0] + __ldg(&out_b2[0]);
}

// ---------------- launch ----------------
extern "C" void kernel_launch(void* const* d_in, const int* in_sizes, int n_in,
                              void* d_out, int out_size)
{
    const float* edge_vec  = (const float*)d_in[0];
    const float* embedding = (const float*)d_in[1];
    const float* phi_W1 = (const float*)d_in[2];
    const float* phi_b1 = (const float*)d_in[3];
    const float* phi_W2 = (const float*)d_in[4];
    const float* phi_b2 = (const float*)d_in[5];
    const float* filt_W = (const float*)d_in[6];
    const float* filt_b = (const float*)d_in[7];
    const float* upd_W1 = (const float*)d_in[8];
    const float* upd_b1 = (const float*)d_in[9];
    const float* upd_W2 = (const float*)d_in[10];
    const float* upd_b2 = (const float*)d_in[11];
    const float* out_W1 = (const float*)d_in[12];
    const float* out_b1 = (const float*)d_in[13];
    const float* out_W2 = (const float*)d_in[14];
    const float* out_b2 = (const float*)d_in[15];
    const float* U_W    = (const float*)d_in[16];
    const float* V_W    = (const float*)d_in[17];
    const int* atom_types = (const int*)d_in[18];
    const int* node_from  = (const int*)d_in[19];
    const int* node_to    = (const int*)d_in[20];
    const int* node_graph_index = (const int*)d_in[21];
    float* out = (float*)d_out;

    init_kernel<<<2048, 256>>>(embedding, atom_types);
    node_phi_kernel<<<(NNODES + 63) / 64, 128>>>(phi_W1, phi_b1, phi_W2, phi_b2);
    edge_kernel<<<NEDGES / 8, 256>>>(edge_vec, filt_W, filt_b, node_from, node_to);
    uv_gemm_kernel<<<(NNODES * 3 + 63) / 64, 256>>>(U_W, V_W);
    uv_reduce_kernel<<<(NNODES * D + 255) / 256, 256>>>();
    update_kernel<<<(NNODES + 31) / 32, 128>>>(upd_W1, upd_b1, upd_W2, upd_b2, node_graph_index);
    out_kernel<<<NGRAPHS, D>>>(out_W1, out_b1, out_W2, out_b2, out);
}

// round 3
// speedup vs baseline: 2.4595x; 1.1622x over previous
#include <cuda_runtime.h>
#include <math.h>

#define D 128
#define NRBF 20
#define NNODES 25000
#define NEDGES 250000
#define NGRAPHS 512

// ---------------- scratch (device globals; no allocation) ----------------
__device__ float g_state0[NNODES * D];
__device__ float g_state_acc[NNODES * D];
__device__ float g_state_vec[NNODES * 3 * D];
__device__ float g_phi[NNODES * 2 * D];         // per-node phi cols 128..383 (m2|m3)
__device__ float g_UV[NNODES * D];
__device__ float g_Vn[NNODES * D];
__device__ float g_graph[NGRAPHS * D];

typedef unsigned long long u64;

__device__ __forceinline__ float silu_f(float x) {
    return x / (1.0f + __expf(-x));
}

__device__ __forceinline__ u64 pk2(float lo, float hi) {
    u64 r;
    asm("mov.b64 %0, {%1, %2};" : "=l"(r) : "r"(__float_as_uint(lo)), "r"(__float_as_uint(hi)));
    return r;
}
__device__ __forceinline__ float2 upk2(u64 v) {
    unsigned lo, hi;
    asm("mov.b64 {%0, %1}, %2;" : "=r"(lo), "=r"(hi) : "l"(v));
    return make_float2(__uint_as_float(lo), __uint_as_float(hi));
}
__device__ __forceinline__ void fma2(u64& acc, u64 a, u64 b) {
    asm("fma.rn.f32x2 %0, %1, %2, %0;" : "+l"(acc) : "l"(a), "l"(b));
}

// ---------------- init ----------------
__global__ void init_kernel(const float* __restrict__ emb, const int* __restrict__ atype) {
    int stride = gridDim.x * blockDim.x;
    int total = NNODES * 3 * D;
    for (int idx = blockIdx.x * blockDim.x + threadIdx.x; idx < total; idx += stride) {
        g_state_vec[idx] = 0.0f;
        if (idx < NNODES * D) {
            int n = idx >> 7;
            int j = idx & 127;
            g_state0[idx] = emb[atype[n] * D + j];
            g_state_acc[idx] = 0.0f;
        }
        if (idx < NGRAPHS * D) g_graph[idx] = 0.0f;
    }
}

// ---------------- per-node phi MLP ----------------
// 64 nodes / block, 128 threads, 8x8 tiles, weights staged in smem, f32x2 FMA.
__global__ __launch_bounds__(128) void node_phi_kernel(
    const float* __restrict__ phi_W1, const float* __restrict__ phi_b1,
    const float* __restrict__ phi_W2, const float* __restrict__ phi_b2)
{
    __shared__ float sA[64][132];
    __shared__ float sW[32][132];
    const int t = threadIdx.x;
    const int n0 = blockIdx.x * 64;

    for (int k = t; k < 64 * 32; k += 128) {
        int row = k >> 5, c4 = k & 31;
        int n = n0 + row;
        float4 v = make_float4(0.f, 0.f, 0.f, 0.f);
        if (n < NNODES) v = ((const float4*)(g_state0 + (size_t)n * D))[c4];
        *(float4*)(&sA[row][c4 * 4]) = v;
    }

    const int ty = t >> 4;
    const int tx = t & 15;
    const int r0 = ty * 8, c0 = tx * 8;

    // GEMM1: hid = silu(S @ phi_W1 + b1)
    u64 acc[8][4];
    #pragma unroll
    for (int i = 0; i < 8; i++)
        #pragma unroll
        for (int j = 0; j < 4; j++) acc[i][j] = 0ull;

    for (int k0 = 0; k0 < D; k0 += 32) {
        __syncthreads();
        for (int k = t; k < 32 * 32; k += 128) {
            int row = k >> 5, c4 = k & 31;
            *(float4*)(&sW[row][c4 * 4]) = __ldg((const float4*)(phi_W1 + (k0 + row) * D + c4 * 4));
        }
        __syncthreads();
        for (int kk = 0; kk < 32; kk++) {
            u64 ad[8];
            #pragma unroll
            for (int i = 0; i < 8; i++) {
                float a = sA[r0 + i][k0 + kk];
                ad[i] = pk2(a, a);
            }
            float4 b0 = *(const float4*)(&sW[kk][c0]);
            float4 b1 = *(const float4*)(&sW[kk][c0 + 4]);
            u64 bp[4] = {pk2(b0.x, b0.y), pk2(b0.z, b0.w), pk2(b1.x, b1.y), pk2(b1.z, b1.w)};
            #pragma unroll
            for (int i = 0; i < 8; i++)
                #pragma unroll
                for (int j = 0; j < 4; j++) fma2(acc[i][j], ad[i], bp[j]);
        }
    }
    __syncthreads();
    #pragma unroll
    for (int j = 0; j < 4; j++) {
        float bias0 = __ldg(&phi_b1[c0 + 2 * j]);
        float bias1 = __ldg(&phi_b1[c0 + 2 * j + 1]);
        #pragma unroll
        for (int i = 0; i < 8; i++) {
            float2 v = upk2(acc[i][j]);
            sA[r0 + i][c0 + 2 * j] = silu_f(v.x + bias0);
            sA[r0 + i][c0 + 2 * j + 1] = silu_f(v.y + bias1);
        }
    }
    __syncthreads();

    // GEMM2: H @ phi_W2[:, 128:384]  (two 128-col passes)
    #pragma unroll 1
    for (int half = 0; half < 2; half++) {
        const int cb = D + half * D;
        u64 acc2[8][4];
        #pragma unroll
        for (int i = 0; i < 8; i++)
            #pragma unroll
            for (int j = 0; j < 4; j++) acc2[i][j] = 0ull;

        for (int k0 = 0; k0 < D; k0 += 32) {
            __syncthreads();
            for (int k = t; k < 32 * 32; k += 128) {
                int row = k >> 5, c4 = k & 31;
                *(float4*)(&sW[row][c4 * 4]) = __ldg((const float4*)(phi_W2 + (k0 + row) * 384 + cb + c4 * 4));
            }
            __syncthreads();
            for (int kk = 0; kk < 32; kk++) {
                u64 ad[8];
                #pragma unroll
                for (int i = 0; i < 8; i++) {
                    float a = sA[r0 + i][k0 + kk];
                    ad[i] = pk2(a, a);
                }
                float4 b0 = *(const float4*)(&sW[kk][c0]);
                float4 b1 = *(const float4*)(&sW[kk][c0 + 4]);
                u64 bp[4] = {pk2(b0.x, b0.y), pk2(b0.z, b0.w), pk2(b1.x, b1.y), pk2(b1.z, b1.w)};
                #pragma unroll
                for (int i = 0; i < 8; i++)
                    #pragma unroll
                    for (int j = 0; j < 4; j++) fma2(acc2[i][j], ad[i], bp[j]);
            }
        }

        #pragma unroll
        for (int i = 0; i < 8; i++) {
            int n = n0 + r0 + i;
            if (n < NNODES) {
                float2 p0 = upk2(acc2[i][0]);
                float2 p1 = upk2(acc2[i][1]);
                float2 p2 = upk2(acc2[i][2]);
                float2 p3 = upk2(acc2[i][3]);
                float4* dst = (float4*)(g_phi + (size_t)n * 256 + half * D + c0);
                dst[0] = make_float4(p0.x + __ldg(&phi_b2[cb + c0 + 0]),
                                     p0.y + __ldg(&phi_b2[cb + c0 + 1]),
                                     p1.x + __ldg(&phi_b2[cb + c0 + 2]),
                                     p1.y + __ldg(&phi_b2[cb + c0 + 3]));
                dst[1] = make_float4(p2.x + __ldg(&phi_b2[cb + c0 + 4]),
                                     p2.y + __ldg(&phi_b2[cb + c0 + 5]),
                                     p3.x + __ldg(&phi_b2[cb + c0 + 6]),
                                     p3.y + __ldg(&phi_b2[cb + c0 + 7]));
            }
        }
    }
}

// ---------------- edge kernel: RBF filter + gather phi[from] + scatter ----------------
__global__ __launch_bounds__(256) void edge_kernel(
    const float* __restrict__ edge_vec,
    const float* __restrict__ filt_W, const float* __restrict__ filt_b,
    const int* __restrict__ node_from, const int* __restrict__ node_to)
{
    __shared__ float sRbf[8][20];
    __shared__ float sFc[8];
    __shared__ float sDist[8];
    __shared__ float sNorm[8][3];
    __shared__ int   sFrom[8];
    __shared__ int   sTo[8];

    const int t = threadIdx.x;
    const int e0 = blockIdx.x * 8;
    const float PI = 3.14159265358979323846f;

    if (t < 8) {
        int e = e0 + t;
        float x = edge_vec[3 * e + 0];
        float y = edge_vec[3 * e + 1];
        float z = edge_vec[3 * e + 2];
        float d = sqrtf(x * x + y * y + z * z);
        float inv = 1.0f / d;
        float fcv = (d < 10.0f) ? 0.5f * (cosf(PI * d * 0.1f) + 1.0f) : 0.0f;
        sDist[t] = d;
        sFc[t] = fcv * inv;
        sNorm[t][0] = x * inv; sNorm[t][1] = y * inv; sNorm[t][2] = z * inv;
        sFrom[t] = node_from[e];
        sTo[t] = node_to[e];
    }
    __syncthreads();
    if (t < 160) {
        int le = t / 20, r = t % 20;
        sRbf[le][r] = sinf((float)(r + 1) * PI * sDist[le] * 0.1f) * sFc[le];
    }
    __syncthreads();

    const int le = t >> 5;
    const int j0 = (t & 31) << 3;
    const float fc = sFc[le] * sDist[le];

    float w[8];
    #pragma unroll
    for (int j = 0; j < 8; j++) w[j] = fc * __ldg(&filt_b[128 + j0 + j]);
    #pragma unroll
    for (int r = 0; r < NRBF; r++) {
        float a = sRbf[le][r];
        float4 b0 = __ldg((const float4*)(filt_W + r * 384 + 128 + j0));
        float4 b1 = __ldg((const float4*)(filt_W + r * 384 + 128 + j0 + 4));
        w[0] += a * b0.x; w[1] += a * b0.y; w[2] += a * b0.z; w[3] += a * b0.w;
        w[4] += a * b1.x; w[5] += a * b1.y; w[6] += a * b1.z; w[7] += a * b1.w;
    }

    const float4* ph = (const float4*)(g_phi + (size_t)sFrom[le] * 256 + j0);
    float4 p0 = ph[0];
    float4 p1 = ph[1];
    float pf[8];
    pf[0] = p0.x * w[0]; pf[1] = p0.y * w[1]; pf[2] = p0.z * w[2]; pf[3] = p0.w * w[3];
    pf[4] = p1.x * w[4]; pf[5] = p1.y * w[5]; pf[6] = p1.z * w[6]; pf[7] = p1.w * w[7];

    const int to = sTo[le];
    if (j0 < 128) {
        float4* dst = (float4*)(g_state_acc + (size_t)to * D + j0);
        atomicAdd(dst,     make_float4(pf[0], pf[1], pf[2], pf[3]));
        atomicAdd(dst + 1, make_float4(pf[4], pf[5], pf[6], pf[7]));
    } else {
        const int jj = j0 - 128;
        float n0 = sNorm[le][0], n1 = sNorm[le][1], n2 = sNorm[le][2];
        float* base = g_state_vec + (size_t)to * (3 * D) + jj;
        atomicAdd((float4*)(base),             make_float4(n0 * pf[0], n0 * pf[1], n0 * pf[2], n0 * pf[3]));
        atomicAdd((float4*)(base + 4),         make_float4(n0 * pf[4], n0 * pf[5], n0 * pf[6], n0 * pf[7]));
        atomicAdd((float4*)(base + D),         make_float4(n1 * pf[0], n1 * pf[1], n1 * pf[2], n1 * pf[3]));
        atomicAdd((float4*)(base + D + 4),     make_float4(n1 * pf[4], n1 * pf[5], n1 * pf[6], n1 * pf[7]));
        atomicAdd((float4*)(base + 2 * D),     make_float4(n2 * pf[0], n2 * pf[1], n2 * pf[2], n2 * pf[3]));
        atomicAdd((float4*)(base + 2 * D + 4), make_float4(n2 * pf[4], n2 * pf[5], n2 * pf[6], n2 * pf[7]));
    }
}

// ---------------- fused UV kernel: Up/Vp GEMM + UV/Vn reduce (no materialization) ----
// 16 nodes (48 rows) / block, 256 threads. Thread owns 1 node x 8 cols, all 3
// vector components -> UV and Vn computed in registers.
__global__ __launch_bounds__(256) void uv_kernel(
    const float* __restrict__ U_W, const float* __restrict__ V_W)
{
    __shared__ float sA[48][132];
    __shared__ float sU[32][132];
    __shared__ float sV[32][132];
    const int t = threadIdx.x;
    const int nb0 = blockIdx.x * 16;
    const int rb = nb0 * 3;
    const int NR = NNODES * 3;

    for (int k = t; k < 48 * 32; k += 256) {
        int row = k >> 5, c4 = k & 31;
        int r = rb + row;
        float4 v = make_float4(0.f, 0.f, 0.f, 0.f);
        if (r < NR) v = ((const float4*)(g_state_vec + (size_t)r * D))[c4];
        *(float4*)(&sA[row][c4 * 4]) = v;
    }

    const int nl = t >> 4;          // node within block
    const int c0 = (t & 15) * 8;    // column group

    u64 au[3][4], av[3][4];
    #pragma unroll
    for (int c = 0; c < 3; c++)
        #pragma unroll
        for (int j = 0; j < 4; j++) { au[c][j] = 0ull; av[c][j] = 0ull; }

    for (int k0 = 0; k0 < D; k0 += 32) {
        __syncthreads();
        for (int k = t; k < 32 * 32; k += 256) {
            int row = k >> 5, c4 = k & 31;
            *(float4*)(&sU[row][c4 * 4]) = __ldg((const float4*)(U_W + (k0 + row) * D + c4 * 4));
            *(float4*)(&sV[row][c4 * 4]) = __ldg((const float4*)(V_W + (k0 + row) * D + c4 * 4));
        }
        __syncthreads();
        for (int kk = 0; kk < 32; kk++) {
            float a0 = sA[nl * 3 + 0][k0 + kk];
            float a1 = sA[nl * 3 + 1][k0 + kk];
            float a2 = sA[nl * 3 + 2][k0 + kk];
            u64 d0 = pk2(a0, a0), d1 = pk2(a1, a1), d2 = pk2(a2, a2);
            float4 u0 = *(const float4*)(&sU[kk][c0]);
            float4 u1 = *(const float4*)(&sU[kk][c0 + 4]);
            float4 v0 = *(const float4*)(&sV[kk][c0]);
            float4 v1 = *(const float4*)(&sV[kk][c0 + 4]);
            u64 bu[4] = {pk2(u0.x, u0.y), pk2(u0.z, u0.w), pk2(u1.x, u1.y), pk2(u1.z, u1.w)};
            u64 bv[4] = {pk2(v0.x, v0.y), pk2(v0.z, v0.w), pk2(v1.x, v1.y), pk2(v1.z, v1.w)};
            #pragma unroll
            for (int j = 0; j < 4; j++) {
                fma2(au[0][j], d0, bu[j]);
                fma2(au[1][j], d1, bu[j]);
                fma2(au[2][j], d2, bu[j]);
                fma2(av[0][j], d0, bv[j]);
                fma2(av[1][j], d1, bv[j]);
                fma2(av[2][j], d2, bv[j]);
            }
        }
    }

    int node = nb0 + nl;
    if (node < NNODES) {
        float uvv[8], vnv[8];
        #pragma unroll
        for (int j = 0; j < 4; j++) {
            float2 A0 = upk2(au[0][j]), A1 = upk2(au[1][j]), A2 = upk2(au[2][j]);
            float2 B0 = upk2(av[0][j]), B1 = upk2(av[1][j]), B2 = upk2(av[2][j]);
            uvv[2 * j]     = A0.x * B0.x + A1.x * B1.x + A2.x * B2.x;
            uvv[2 * j + 1] = A0.y * B0.y + A1.y * B1.y + A2.y * B2.y;
            vnv[2 * j]     = sqrtf(B0.x * B0.x + B1.x * B1.x + B2.x * B2.x);
            vnv[2 * j + 1] = sqrtf(B0.y * B0.y + B1.y * B1.y + B2.y * B2.y);
        }
        float4* du = (float4*)(g_UV + (size_t)node * D + c0);
        float4* dv = (float4*)(g_Vn + (size_t)node * D + c0);
        du[0] = make_float4(uvv[0], uvv[1], uvv[2], uvv[3]);
        du[1] = make_float4(uvv[4], uvv[5], uvv[6], uvv[7]);
        dv[0] = make_float4(vnv[0], vnv[1], vnv[2], vnv[3]);
        dv[1] = make_float4(vnv[4], vnv[5], vnv[6], vnv[7]);
    }
}

// ---------------- node update MLP + segment-sum ----------------
// 32 nodes / block, 128 threads, 4x8 tiles, weights staged, f32x2.
__global__ __launch_bounds__(128) void update_kernel(
    const float* __restrict__ upd_W1, const float* __restrict__ upd_b1,
    const float* __restrict__ upd_W2, const float* __restrict__ upd_b2,
    const int* __restrict__ node_graph_index)
{
    __shared__ float sA[32][260];    // 0..127: Vn (later hid), 128..255: state
    __shared__ float sW[32][264];    // staged weight tiles (GEMM2 uses 256 cols)
    const int t = threadIdx.x;
    const int n0 = blockIdx.x * 32;

    for (int k = t; k < 32 * 64; k += 128) {
        int row = k >> 6, c4 = k & 63;
        int n = n0 + row;
        float4 v = make_float4(0.f, 0.f, 0.f, 0.f);
        if (n < NNODES) {
            if (c4 < 32) {
                v = ((const float4*)(g_Vn + (size_t)n * D))[c4];
            } else {
                float4 s0 = ((const float4*)(g_state0 + (size_t)n * D))[c4 - 32];
                float4 s1 = ((const float4*)(g_state_acc + (size_t)n * D))[c4 - 32];
                v = make_float4(s0.x + s1.x, s0.y + s1.y, s0.z + s1.z, s0.w + s1.w);
            }
        }
        *(float4*)(&sA[row][c4 * 4]) = v;
    }

    const int ty = t >> 4;
    const int tx = t & 15;
    const int r0 = ty * 4, c0 = tx * 8;

    // GEMM1: hid = silu(h @ upd_W1 + b1), K=256
    u64 acc[4][4];
    #pragma unroll
    for (int i = 0; i < 4; i++)
        #pragma unroll
        for (int j = 0; j < 4; j++) acc[i][j] = 0ull;

    for (int k0 = 0; k0 < 2 * D; k0 += 32) {
        __syncthreads();
        for (int k = t; k < 32 * 32; k += 128) {
            int row = k >> 5, c4 = k & 31;
            *(float4*)(&sW[row][c4 * 4]) = __ldg((const float4*)(upd_W1 + (k0 + row) * D + c4 * 4));
        }
        __syncthreads();
        for (int kk = 0; kk < 32; kk++) {
            u64 ad[4];
            #pragma unroll
            for (int i = 0; i < 4; i++) {
                float a = sA[r0 + i][k0 + kk];
                ad[i] = pk2(a, a);
            }
            float4 b0 = *(const float4*)(&sW[kk][c0]);
            float4 b1 = *(const float4*)(&sW[kk][c0 + 4]);
            u64 bp[4] = {pk2(b0.x, b0.y), pk2(b0.z, b0.w), pk2(b1.x, b1.y), pk2(b1.z, b1.w)};
            #pragma unroll
            for (int i = 0; i < 4; i++)
                #pragma unroll
                for (int j = 0; j < 4; j++) fma2(acc[i][j], ad[i], bp[j]);
        }
    }
    __syncthreads();
    #pragma unroll
    for (int j = 0; j < 4; j++) {
        float bias0 = __ldg(&upd_b1[c0 + 2 * j]);
        float bias1 = __ldg(&upd_b1[c0 + 2 * j + 1]);
        #pragma unroll
        for (int i = 0; i < 4; i++) {
            float2 v = upk2(acc[i][j]);
            sA[r0 + i][c0 + 2 * j] = silu_f(v.x + bias0);
            sA[r0 + i][c0 + 2 * j + 1] = silu_f(v.y + bias1);
        }
    }
    __syncthreads();

    // GEMM2: hid @ upd_W2[:, 128:384], both halves in one pass (staged 256 cols)
    u64 asv[4][4], ass[4][4];
    #pragma unroll
    for (int i = 0; i < 4; i++)
        #pragma unroll
        for (int j = 0; j < 4; j++) { asv[i][j] = 0ull; ass[i][j] = 0ull; }

    for (int k0 = 0; k0 < D; k0 += 32) {
        __syncthreads();
        for (int k = t; k < 32 * 64; k += 128) {
            int row = k >> 6, c4 = k & 63;
            *(float4*)(&sW[row][c4 * 4]) = __ldg((const float4*)(upd_W2 + (k0 + row) * 384 + 128 + c4 * 4));
        }
        __syncthreads();
        for (int kk = 0; kk < 32; kk++) {
            u64 ad[4];
            #pragma unroll
            for (int i = 0; i < 4; i++) {
                float a = sA[r0 + i][k0 + kk];
                ad[i] = pk2(a, a);
            }
            float4 b0 = *(const float4*)(&sW[kk][c0]);
            float4 b1 = *(const float4*)(&sW[kk][c0 + 4]);
            float4 b2 = *(const float4*)(&sW[kk][128 + c0]);
            float4 b3 = *(const float4*)(&sW[kk][128 + c0 + 4]);
            u64 bsv[4] = {pk2(b0.x, b0.y), pk2(b0.z, b0.w), pk2(b1.x, b1.y), pk2(b1.z, b1.w)};
            u64 bss[4] = {pk2(b2.x, b2.y), pk2(b2.z, b2.w), pk2(b3.x, b3.y), pk2(b3.z, b3.w)};
            #pragma unroll
            for (int i = 0; i < 4; i++)
                #pragma unroll
                for (int j = 0; j < 4; j++) {
                    fma2(asv[i][j], ad[i], bsv[j]);
                    fma2(ass[i][j], ad[i], bss[j]);
                }
        }
    }

    int base = __ldg(&node_graph_index[0]);
    #pragma unroll
    for (int i = 0; i < 4; i++) {
        int n = n0 + r0 + i;
        if (n < NNODES) {
            int g = __ldg(&node_graph_index[n]) - base;
            float* dst = g_graph + (size_t)g * D + c0;
            float vals[8];
            #pragma unroll
            for (int j = 0; j < 4; j++) {
                float2 sv = upk2(asv[i][j]);
                float2 ss = upk2(ass[i][j]);
                float uv0 = g_UV[(size_t)n * D + c0 + 2 * j];
                float uv1 = g_UV[(size_t)n * D + c0 + 2 * j + 1];
                float a_sv0 = sv.x + __ldg(&upd_b2[D + c0 + 2 * j]);
                float a_sv1 = sv.y + __ldg(&upd_b2[D + c0 + 2 * j + 1]);
                float a_ss0 = ss.x + __ldg(&upd_b2[2 * D + c0 + 2 * j]);
                float a_ss1 = ss.y + __ldg(&upd_b2[2 * D + c0 + 2 * j + 1]);
                vals[2 * j]     = sA[r0 + i][D + c0 + 2 * j]     + uv0 * a_sv0 + a_ss0;
                vals[2 * j + 1] = sA[r0 + i][D + c0 + 2 * j + 1] + uv1 * a_sv1 + a_ss1;
            }
            atomicAdd((float4*)dst,       make_float4(vals[0], vals[1], vals[2], vals[3]));
            atomicAdd((float4*)(dst + 4), make_float4(vals[4], vals[5], vals[6], vals[7]));
        }
    }
}

// ---------------- output MLP: 512 graphs ----------------
__global__ void out_kernel(
    const float* __restrict__ out_W1, const float* __restrict__ out_b1,
    const float* __restrict__ out_W2, const float* __restrict__ out_b2,
    float* __restrict__ out)
{
    __shared__ float sG[D];
    __shared__ float sRed[D];
    const int g = blockIdx.x;
    const int t = threadIdx.x;
    sG[t] = g_graph[(size_t)g * D + t];
    __syncthreads();
    float x = 0.f;
    #pragma unroll 8
    for (int k = 0; k < D; k++) x += sG[k] * __ldg(&out_W1[k * D + t]);
    x += __ldg(&out_b1[t]);
    float p = silu_f(x) * __ldg(&out_W2[t]);
    sRed[t] = p;
    __syncthreads();
    for (int s = 64; s > 0; s >>= 1) {
        if (t < s) sRed[t] += sRed[t + s];
        __syncthreads();
    }
    if (t == 0) out[g] = sRed[0] + __ldg(&out_b2[0]);
}

// ---------------- launch ----------------
extern "C" void kernel_launch(void* const* d_in, const int* in_sizes, int n_in,
                              void* d_out, int out_size)
{
    const float* edge_vec  = (const float*)d_in[0];
    const float* embedding = (const float*)d_in[1];
    const float* phi_W1 = (const float*)d_in[2];
    const float* phi_b1 = (const float*)d_in[3];
    const float* phi_W2 = (const float*)d_in[4];
    const float* phi_b2 = (const float*)d_in[5];
    const float* filt_W = (const float*)d_in[6];
    const float* filt_b = (const float*)d_in[7];
    const float* upd_W1 = (const float*)d_in[8];
    const float* upd_b1 = (const float*)d_in[9];
    const float* upd_W2 = (const float*)d_in[10];
    const float* upd_b2 = (const float*)d_in[11];
    const float* out_W1 = (const float*)d_in[12];
    const float* out_b1 = (const float*)d_in[13];
    const float* out_W2 = (const float*)d_in[14];
    const float* out_b2 = (const float*)d_in[15];
    const float* U_W    = (const float*)d_in[16];
    const float* V_W    = (const float*)d_in[17];
    const int* atom_types = (const int*)d_in[18];
    const int* node_from  = (const int*)d_in[19];
    const int* node_to    = (const int*)d_in[20];
    const int* node_graph_index = (const int*)d_in[21];
    float* out = (float*)d_out;

    init_kernel<<<2048, 256>>>(embedding, atom_types);
    node_phi_kernel<<<(NNODES + 63) / 64, 128>>>(phi_W1, phi_b1, phi_W2, phi_b2);
    edge_kernel<<<NEDGES / 8, 256>>>(edge_vec, filt_W, filt_b, node_from, node_to);
    uv_kernel<<<(NNODES + 15) / 16, 256>>>(U_W, V_W);
    update_kernel<<<(NNODES + 31) / 32, 128>>>(upd_W1, upd_b1, upd_W2, upd_b2, node_graph_index);
    out_kernel<<<NGRAPHS, D>>>(out_W1, out_b1, out_W2, out_b2, out);
}